// round 7
// baseline (speedup 1.0000x reference)
#include <cuda_runtime.h>
#include <cuda_bf16.h>
#include <cstdint>
#include <cstddef>

// Problem constants
#define BB 2
#define LL 1024
#define HH 2048
#define HD 64
#define NQ 32
#define NK 4
#define NPREV 28

// Scratch (device globals; allocation at module load, allowed)
__device__ float g_Q[(size_t)BB * NQ * LL * HD];   // [B, 32, L, 64]
__device__ float g_K[(size_t)BB * NQ * LL * HD];   // stacked KV cache
__device__ float g_V[(size_t)BB * NQ * LL * HD];
__device__ float g_AO[(size_t)BB * LL * (NQ * HD)]; // attn out, [B, L, 2048]

// ---------------------------------------------------------------------------
// Generic SGEMM: C[m,n] = sum_k A[m,k] * W[n,k]   (A: [M,K] rm, W: [N,K] rm)
// scatter=1: write C to [B, head_off+h, L, HD] layout with n = h*64+d, m = b*L+l
// scatter=0: plain row-major C[m*N+n]
// BM=BN=128, BK=16, 256 threads, 8x8 per thread.
// ---------------------------------------------------------------------------
__global__ void __launch_bounds__(256) sgemm_nt(
    const float* __restrict__ A, const float* __restrict__ W,
    float* __restrict__ C, int M, int N, int K, int scatter, int head_off)
{
    __shared__ float As[16][128];
    __shared__ float Bs[16][128];

    const int t  = threadIdx.x;
    const int tx = t & 15;
    const int ty = t >> 4;
    const int row0 = blockIdx.y * 128;
    const int col0 = blockIdx.x * 128;

    float acc[8][8];
#pragma unroll
    for (int i = 0; i < 8; i++)
#pragma unroll
        for (int j = 0; j < 8; j++) acc[i][j] = 0.0f;

    for (int bk = 0; bk < K; bk += 16) {
        // Load A tile: 128 rows x 16 cols = 512 float4
#pragma unroll
        for (int q = 0; q < 2; q++) {
            int f  = t * 2 + q;        // 0..511
            int r  = f >> 2;
            int c4 = f & 3;
            float4 v = *(const float4*)(A + (size_t)(row0 + r) * K + bk + c4 * 4);
            As[c4 * 4 + 0][r] = v.x;
            As[c4 * 4 + 1][r] = v.y;
            As[c4 * 4 + 2][r] = v.z;
            As[c4 * 4 + 3][r] = v.w;
        }
        // Load W tile (rows = output cols)
#pragma unroll
        for (int q = 0; q < 2; q++) {
            int f  = t * 2 + q;
            int r  = f >> 2;
            int c4 = f & 3;
            float4 v = *(const float4*)(W + (size_t)(col0 + r) * K + bk + c4 * 4);
            Bs[c4 * 4 + 0][r] = v.x;
            Bs[c4 * 4 + 1][r] = v.y;
            Bs[c4 * 4 + 2][r] = v.z;
            Bs[c4 * 4 + 3][r] = v.w;
        }
        __syncthreads();

#pragma unroll
        for (int kk = 0; kk < 16; kk++) {
            float4 a0 = *(const float4*)&As[kk][ty * 8];
            float4 a1 = *(const float4*)&As[kk][ty * 8 + 4];
            float4 b0 = *(const float4*)&Bs[kk][tx * 8];
            float4 b1 = *(const float4*)&Bs[kk][tx * 8 + 4];
            float a[8] = {a0.x, a0.y, a0.z, a0.w, a1.x, a1.y, a1.z, a1.w};
            float b[8] = {b0.x, b0.y, b0.z, b0.w, b1.x, b1.y, b1.z, b1.w};
#pragma unroll
            for (int i = 0; i < 8; i++)
#pragma unroll
                for (int j = 0; j < 8; j++)
                    acc[i][j] = fmaf(a[i], b[j], acc[i][j]);
        }
        __syncthreads();
    }

    // Epilogue
#pragma unroll
    for (int i = 0; i < 8; i++) {
        int m = row0 + ty * 8 + i;
#pragma unroll
        for (int j = 0; j < 8; j++) {
            int n = col0 + tx * 8 + j;
            if (scatter) {
                int bb = m >> 10, l = m & 1023;
                int hh = n >> 6,  d = n & 63;
                C[((size_t)((bb * 32 + head_off + hh) * 1024 + l)) * 64 + d] = acc[i][j];
            } else {
                C[(size_t)m * N + n] = acc[i][j];
            }
        }
    }
}

// ---------------------------------------------------------------------------
// RoPE + cache gather.
// Thread handles one (b, h, l, d) with d < 32, processing the pair (d, d+32).
// Q: rope in place (g_Q already holds projections for all 32 heads).
// K: h<28 -> read prev_k, rope, write g_K; h>=28 -> rope g_K in place.
// V: h<28 -> copy prev_v into g_V (h>=28 already written by GEMM).
// ---------------------------------------------------------------------------
__global__ void __launch_bounds__(256) rope_gather_kernel(
    const float* __restrict__ prev_k, const float* __restrict__ prev_v,
    const float* __restrict__ cosp,   const float* __restrict__ sinp)
{
    unsigned t = blockIdx.x * 256u + threadIdx.x;   // 0 .. 2^21-1
    int d = t & 31;
    int l = (t >> 5) & 1023;
    int h = (t >> 15) & 31;
    int b = t >> 20;

    float c = cosp[l * 64 + d];
    float s = sinp[l * 64 + d];

    size_t base = ((size_t)(b * 32 + h) * 1024 + l) * 64;

    // Q
    {
        float* q = g_Q + base;
        float x1 = q[d], x2 = q[d + 32];
        q[d]      = x1 * c - x2 * s;
        q[d + 32] = x2 * c + x1 * s;
    }
    // K
    {
        float* k = g_K + base;
        float y1, y2;
        if (h < NPREV) {
            const float* pk = prev_k + ((size_t)(b * NPREV + h) * 1024 + l) * 64;
            y1 = pk[d]; y2 = pk[d + 32];
        } else {
            y1 = k[d]; y2 = k[d + 32];
        }
        k[d]      = y1 * c - y2 * s;
        k[d + 32] = y2 * c + y1 * s;
    }
    // V copy
    if (h < NPREV) {
        const float* pv = prev_v + ((size_t)(b * NPREV + h) * 1024 + l) * 64;
        float* v = g_V + base;
        v[d]      = pv[d];
        v[d + 32] = pv[d + 32];
    }
}

// ---------------------------------------------------------------------------
// Flash attention (fp32, causal). BR=BC=64, 256 threads.
// Thread (ty,tx): ty=t/16 owns S/O rows ty*4+i; columns mapped c = jj*16+tx.
// smem ld=68 (float4-aligned, conflict-free for the strided-row pattern).
// Writes O to g_AO in [B, L, 32*64] layout.
// ---------------------------------------------------------------------------
#define FA_LD 68
#define FA_SMEM (3 * 64 * FA_LD * 4)

__global__ void __launch_bounds__(256) flash_kernel(
    const float* __restrict__ Q, const float* __restrict__ K,
    const float* __restrict__ V, float* __restrict__ AO)
{
    extern __shared__ float sm[];
    float* Qs = sm;                      // 64 x FA_LD
    float* Ks = sm + 64 * FA_LD;         // K tile, reused for P
    float* Vs = sm + 2 * 64 * FA_LD;

    const int t  = threadIdx.x;
    const int tx = t & 15;
    const int ty = t >> 4;
    const int qt = blockIdx.x;
    const int h  = blockIdx.y;
    const int b  = blockIdx.z;
    const int q0 = qt * 64;

    const size_t bh_off = (size_t)(b * 32 + h) * 1024 * 64;
    const float* Qp = Q + bh_off;
    const float* Kp = K + bh_off;
    const float* Vp = V + bh_off;

    // Load Q tile (64x64): 1024 float4, 4 per thread
#pragma unroll
    for (int q = 0; q < 4; q++) {
        int f  = q * 256 + t;
        int r  = f >> 4;
        int c4 = f & 15;
        float4 v = *(const float4*)(Qp + (size_t)(q0 + r) * 64 + c4 * 4);
        float* dst = Qs + r * FA_LD + c4 * 4;
        dst[0] = v.x; dst[1] = v.y; dst[2] = v.z; dst[3] = v.w;
    }

    float m_i[4], l_i[4], o_[4][4];
#pragma unroll
    for (int i = 0; i < 4; i++) {
        m_i[i] = -1e30f; l_i[i] = 0.0f;
#pragma unroll
        for (int j = 0; j < 4; j++) o_[i][j] = 0.0f;
    }

    for (int j = 0; j <= qt; j++) {
        __syncthreads();   // protect Ks(=P)/Vs from previous iteration; covers Q load too
        // Load K, V tiles
#pragma unroll
        for (int q = 0; q < 4; q++) {
            int f  = q * 256 + t;
            int r  = f >> 4;
            int c4 = f & 15;
            size_t goff = (size_t)(j * 64 + r) * 64 + c4 * 4;
            float4 kv = *(const float4*)(Kp + goff);
            float* dk = Ks + r * FA_LD + c4 * 4;
            dk[0] = kv.x; dk[1] = kv.y; dk[2] = kv.z; dk[3] = kv.w;
            float4 vv = *(const float4*)(Vp + goff);
            float* dv = Vs + r * FA_LD + c4 * 4;
            dv[0] = vv.x; dv[1] = vv.y; dv[2] = vv.z; dv[3] = vv.w;
        }
        __syncthreads();

        // S = Q @ K^T (4x4 per thread; cols c = jj*16+tx)
        float s_[4][4];
#pragma unroll
        for (int i = 0; i < 4; i++)
#pragma unroll
            for (int jj = 0; jj < 4; jj++) s_[i][jj] = 0.0f;

#pragma unroll
        for (int d4 = 0; d4 < 16; d4++) {
            float4 a[4], kk[4];
#pragma unroll
            for (int i = 0; i < 4; i++)
                a[i] = *(const float4*)(Qs + (ty * 4 + i) * FA_LD + d4 * 4);
#pragma unroll
            for (int jj = 0; jj < 4; jj++)
                kk[jj] = *(const float4*)(Ks + (jj * 16 + tx) * FA_LD + d4 * 4);
#pragma unroll
            for (int i = 0; i < 4; i++)
#pragma unroll
                for (int jj = 0; jj < 4; jj++) {
                    s_[i][jj] = fmaf(a[i].x, kk[jj].x, s_[i][jj]);
                    s_[i][jj] = fmaf(a[i].y, kk[jj].y, s_[i][jj]);
                    s_[i][jj] = fmaf(a[i].z, kk[jj].z, s_[i][jj]);
                    s_[i][jj] = fmaf(a[i].w, kk[jj].w, s_[i][jj]);
                }
        }

        const float scale = 0.125f;  // 64^-0.5
#pragma unroll
        for (int i = 0; i < 4; i++)
#pragma unroll
            for (int jj = 0; jj < 4; jj++) s_[i][jj] *= scale;

        if (j == qt) {  // diagonal tile causal mask (local row/col offsets match)
#pragma unroll
            for (int i = 0; i < 4; i++)
#pragma unroll
                for (int jj = 0; jj < 4; jj++)
                    if ((jj * 16 + tx) > (ty * 4 + i)) s_[i][jj] = -1e30f;
        }

        // Online softmax per row (replicated state across 16-lane row group)
#pragma unroll
        for (int i = 0; i < 4; i++) {
            float mx = fmaxf(fmaxf(s_[i][0], s_[i][1]), fmaxf(s_[i][2], s_[i][3]));
#pragma unroll
            for (int off = 1; off < 16; off <<= 1)
                mx = fmaxf(mx, __shfl_xor_sync(0xffffffffu, mx, off));
            float mnew = fmaxf(m_i[i], mx);
            float corr = __expf(m_i[i] - mnew);
            float rs = 0.0f;
#pragma unroll
            for (int jj = 0; jj < 4; jj++) {
                s_[i][jj] = __expf(s_[i][jj] - mnew);
                rs += s_[i][jj];
            }
#pragma unroll
            for (int off = 1; off < 16; off <<= 1)
                rs += __shfl_xor_sync(0xffffffffu, rs, off);
            l_i[i] = l_i[i] * corr + rs;
            m_i[i] = mnew;
#pragma unroll
            for (int jj = 0; jj < 4; jj++) o_[i][jj] *= corr;
        }

        __syncthreads();  // everyone done reading Ks
        // Stage P into Ks
#pragma unroll
        for (int i = 0; i < 4; i++)
#pragma unroll
            for (int jj = 0; jj < 4; jj++)
                Ks[(ty * 4 + i) * FA_LD + jj * 16 + tx] = s_[i][jj];
        __syncthreads();

        // O += P @ V
#pragma unroll
        for (int c4 = 0; c4 < 16; c4++) {
            float4 p4[4];
#pragma unroll
            for (int i = 0; i < 4; i++)
                p4[i] = *(const float4*)(Ks + (ty * 4 + i) * FA_LD + c4 * 4);
#pragma unroll
            for (int cc = 0; cc < 4; cc++) {
                float vv[4];
#pragma unroll
                for (int jj = 0; jj < 4; jj++)
                    vv[jj] = Vs[(c4 * 4 + cc) * FA_LD + jj * 16 + tx];
#pragma unroll
                for (int i = 0; i < 4; i++) {
                    float pval = (cc == 0) ? p4[i].x : (cc == 1) ? p4[i].y
                               : (cc == 2) ? p4[i].z : p4[i].w;
#pragma unroll
                    for (int jj = 0; jj < 4; jj++)
                        o_[i][jj] = fmaf(pval, vv[jj], o_[i][jj]);
                }
            }
        }
    }

    // Normalize + write to [B, L, 32*64]
#pragma unroll
    for (int i = 0; i < 4; i++) {
        float rl = 1.0f / l_i[i];
        size_t row = (size_t)b * 1024 + (q0 + ty * 4 + i);
#pragma unroll
        for (int jj = 0; jj < 4; jj++)
            AO[row * 2048 + h * 64 + jj * 16 + tx] = o_[i][jj] * rl;
    }
}

// ---------------------------------------------------------------------------
// Launch
// Inputs (metadata order): hidden_states, prev_k, prev_v, Wq, Wk, Wv, Wo,
//                          cos, sin, attention_mask(ignored: fixed causal tril)
// ---------------------------------------------------------------------------
extern "C" void kernel_launch(void* const* d_in, const int* in_sizes, int n_in,
                              void* d_out, int out_size)
{
    const float* hs   = (const float*)d_in[0];
    const float* pk   = (const float*)d_in[1];
    const float* pv   = (const float*)d_in[2];
    const float* Wq   = (const float*)d_in[3];
    const float* Wk   = (const float*)d_in[4];
    const float* Wv   = (const float*)d_in[5];
    const float* Wo   = (const float*)d_in[6];
    const float* cosp = (const float*)d_in[7];
    const float* sinp = (const float*)d_in[8];
    float* out = (float*)d_out;

    float *Qb, *Kb, *Vb, *AO;
    cudaGetSymbolAddress((void**)&Qb, g_Q);
    cudaGetSymbolAddress((void**)&Kb, g_K);
    cudaGetSymbolAddress((void**)&Vb, g_V);
    cudaGetSymbolAddress((void**)&AO, g_AO);

    cudaFuncSetAttribute(flash_kernel,
                         cudaFuncAttributeMaxDynamicSharedMemorySize, FA_SMEM);

    // QKV projections (scatter epilogue into [B, head, L, HD])
    sgemm_nt<<<dim3(16, 16), 256>>>(hs, Wq, Qb, 2048, 2048, 2048, 1, 0);
    sgemm_nt<<<dim3(2, 16),  256>>>(hs, Wk, Kb, 2048, 256,  2048, 1, NPREV);
    sgemm_nt<<<dim3(2, 16),  256>>>(hs, Wv, Vb, 2048, 256,  2048, 1, NPREV);

    // Cache gather + RoPE (2^21 pair-threads)
    rope_gather_kernel<<<8192, 256>>>(pk, pv, cosp, sinp);

    // Causal flash attention -> g_AO [B, L, 2048]
    flash_kernel<<<dim3(16, 32, 2), 256, FA_SMEM>>>(Qb, Kb, Vb, AO);

    // Output projection
    sgemm_nt<<<dim3(16, 16), 256>>>(AO, Wo, out, 2048, 2048, 2048, 0, 0);
}

// round 8
// speedup vs baseline: 1.2205x; 1.2205x over previous
#include <cuda_runtime.h>
#include <cuda_bf16.h>
#include <mma.h>
#include <cstdint>
#include <cstddef>

using namespace nvcuda;

// Problem constants
#define BB 2
#define LL 1024
#define HH 2048
#define HD 64
#define NQ 32
#define NK 4
#define NPREV 28

// Scratch (device globals)
__device__ float g_Q[(size_t)BB * NQ * LL * HD];
__device__ float g_K[(size_t)BB * NQ * LL * HD];
__device__ float g_V[(size_t)BB * NQ * LL * HD];
__device__ float g_AO[(size_t)BB * LL * (NQ * HD)];

// ---------------------------------------------------------------------------
// TF32 tensor-core GEMM: C[m,n] = sum_k A[m,k] * W[n,k]
// A: [M,K] rm, W: [N,K] rm. BM=BN=128, BK=32, 256 threads, wmma m16n16k8.
// scatter=1: n=(h,d) m=(b,l) -> C[((b*32+head_off+h)*1024+l)*64+d]
// ---------------------------------------------------------------------------
#define GLD 36   // smem leading dim (floats): 144B, 16B-aligned rows, pad-4

__global__ void __launch_bounds__(256) gemm_tf32(
    const float* __restrict__ A, const float* __restrict__ W,
    float* __restrict__ C, int M, int N, int K, int scatter, int head_off)
{
    __shared__ float As[128][GLD];
    __shared__ float Bs[128][GLD];

    const int t    = threadIdx.x;
    const int warp = t >> 5;
    const int wm   = warp & 3;   // 4 warps along M (32 rows each)
    const int wn   = warp >> 2;  // 2 warps along N (64 cols each)
    const int row0 = blockIdx.y * 128;
    const int col0 = blockIdx.x * 128;

    wmma::fragment<wmma::accumulator, 16, 16, 8, float> acc[2][4];
#pragma unroll
    for (int i = 0; i < 2; i++)
#pragma unroll
        for (int j = 0; j < 4; j++) wmma::fill_fragment(acc[i][j], 0.0f);

    for (int bk = 0; bk < K; bk += 32) {
        // Fill smem (convert to tf32 once here; fragments load raw after)
#pragma unroll
        for (int q = 0; q < 4; q++) {
            int f  = q * 256 + t;          // 0..1023
            int r  = f >> 3;
            int c4 = f & 7;
            float4 va = *(const float4*)(A + (size_t)(row0 + r) * K + bk + c4 * 4);
            float* da = &As[r][c4 * 4];
            da[0] = wmma::__float_to_tf32(va.x);
            da[1] = wmma::__float_to_tf32(va.y);
            da[2] = wmma::__float_to_tf32(va.z);
            da[3] = wmma::__float_to_tf32(va.w);
            float4 vb = *(const float4*)(W + (size_t)(col0 + r) * K + bk + c4 * 4);
            float* db = &Bs[r][c4 * 4];
            db[0] = wmma::__float_to_tf32(vb.x);
            db[1] = wmma::__float_to_tf32(vb.y);
            db[2] = wmma::__float_to_tf32(vb.z);
            db[3] = wmma::__float_to_tf32(vb.w);
        }
        __syncthreads();

#pragma unroll
        for (int ks = 0; ks < 4; ks++) {
            wmma::fragment<wmma::matrix_a, 16, 16, 8, wmma::precision::tf32,
                           wmma::row_major> af[2];
#pragma unroll
            for (int i = 0; i < 2; i++)
                wmma::load_matrix_sync(af[i], &As[wm * 32 + i * 16][ks * 8], GLD);
#pragma unroll
            for (int j = 0; j < 4; j++) {
                wmma::fragment<wmma::matrix_b, 16, 16, 8, wmma::precision::tf32,
                               wmma::col_major> bf;
                wmma::load_matrix_sync(bf, &Bs[wn * 64 + j * 16][ks * 8], GLD);
#pragma unroll
                for (int i = 0; i < 2; i++)
                    wmma::mma_sync(acc[i][j], af[i], bf, acc[i][j]);
            }
        }
        __syncthreads();
    }

    // Epilogue: each 16x16 tile stores directly (never straddles head/batch)
#pragma unroll
    for (int i = 0; i < 2; i++) {
        int m0 = row0 + wm * 32 + i * 16;
#pragma unroll
        for (int j = 0; j < 4; j++) {
            int n0 = col0 + wn * 64 + j * 16;
            if (scatter) {
                int b = m0 >> 10, l = m0 & 1023;
                int h = n0 >> 6,  d = n0 & 63;
                float* dst = C + ((size_t)((b * 32 + head_off + h) * 1024 + l)) * 64 + d;
                wmma::store_matrix_sync(dst, acc[i][j], 64, wmma::mem_row_major);
            } else {
                wmma::store_matrix_sync(C + (size_t)m0 * N + n0, acc[i][j], N,
                                        wmma::mem_row_major);
            }
        }
    }
}

// ---------------------------------------------------------------------------
// RoPE + cache gather (unchanged)
// ---------------------------------------------------------------------------
__global__ void __launch_bounds__(256) rope_gather_kernel(
    const float* __restrict__ prev_k, const float* __restrict__ prev_v,
    const float* __restrict__ cosp,   const float* __restrict__ sinp)
{
    unsigned t = blockIdx.x * 256u + threadIdx.x;
    int d = t & 31;
    int l = (t >> 5) & 1023;
    int h = (t >> 15) & 31;
    int b = t >> 20;

    float c = cosp[l * 64 + d];
    float s = sinp[l * 64 + d];

    size_t base = ((size_t)(b * 32 + h) * 1024 + l) * 64;

    {
        float* q = g_Q + base;
        float x1 = q[d], x2 = q[d + 32];
        q[d]      = x1 * c - x2 * s;
        q[d + 32] = x2 * c + x1 * s;
    }
    {
        float* k = g_K + base;
        float y1, y2;
        if (h < NPREV) {
            const float* pk = prev_k + ((size_t)(b * NPREV + h) * 1024 + l) * 64;
            y1 = pk[d]; y2 = pk[d + 32];
        } else {
            y1 = k[d]; y2 = k[d + 32];
        }
        k[d]      = y1 * c - y2 * s;
        k[d + 32] = y2 * c + y1 * s;
    }
    if (h < NPREV) {
        const float* pv = prev_v + ((size_t)(b * NPREV + h) * 1024 + l) * 64;
        float* v = g_V + base;
        v[d]      = pv[d];
        v[d + 32] = pv[d + 32];
    }
}

// ---------------------------------------------------------------------------
// Flash attention (fp32, causal) — unchanged from R7 passing version
// ---------------------------------------------------------------------------
#define FA_LD 68
#define FA_SMEM (3 * 64 * FA_LD * 4)

__global__ void __launch_bounds__(256) flash_kernel(
    const float* __restrict__ Q, const float* __restrict__ K,
    const float* __restrict__ V, float* __restrict__ AO)
{
    extern __shared__ float sm[];
    float* Qs = sm;
    float* Ks = sm + 64 * FA_LD;
    float* Vs = sm + 2 * 64 * FA_LD;

    const int t  = threadIdx.x;
    const int tx = t & 15;
    const int ty = t >> 4;
    const int qt = blockIdx.x;
    const int h  = blockIdx.y;
    const int b  = blockIdx.z;
    const int q0 = qt * 64;

    const size_t bh_off = (size_t)(b * 32 + h) * 1024 * 64;
    const float* Qp = Q + bh_off;
    const float* Kp = K + bh_off;
    const float* Vp = V + bh_off;

#pragma unroll
    for (int q = 0; q < 4; q++) {
        int f  = q * 256 + t;
        int r  = f >> 4;
        int c4 = f & 15;
        float4 v = *(const float4*)(Qp + (size_t)(q0 + r) * 64 + c4 * 4);
        float* dst = Qs + r * FA_LD + c4 * 4;
        dst[0] = v.x; dst[1] = v.y; dst[2] = v.z; dst[3] = v.w;
    }

    float m_i[4], l_i[4], o_[4][4];
#pragma unroll
    for (int i = 0; i < 4; i++) {
        m_i[i] = -1e30f; l_i[i] = 0.0f;
#pragma unroll
        for (int j = 0; j < 4; j++) o_[i][j] = 0.0f;
    }

    for (int j = 0; j <= qt; j++) {
        __syncthreads();
#pragma unroll
        for (int q = 0; q < 4; q++) {
            int f  = q * 256 + t;
            int r  = f >> 4;
            int c4 = f & 15;
            size_t goff = (size_t)(j * 64 + r) * 64 + c4 * 4;
            float4 kv = *(const float4*)(Kp + goff);
            float* dk = Ks + r * FA_LD + c4 * 4;
            dk[0] = kv.x; dk[1] = kv.y; dk[2] = kv.z; dk[3] = kv.w;
            float4 vv = *(const float4*)(Vp + goff);
            float* dv = Vs + r * FA_LD + c4 * 4;
            dv[0] = vv.x; dv[1] = vv.y; dv[2] = vv.z; dv[3] = vv.w;
        }
        __syncthreads();

        float s_[4][4];
#pragma unroll
        for (int i = 0; i < 4; i++)
#pragma unroll
            for (int jj = 0; jj < 4; jj++) s_[i][jj] = 0.0f;

#pragma unroll
        for (int d4 = 0; d4 < 16; d4++) {
            float4 a[4], kk[4];
#pragma unroll
            for (int i = 0; i < 4; i++)
                a[i] = *(const float4*)(Qs + (ty * 4 + i) * FA_LD + d4 * 4);
#pragma unroll
            for (int jj = 0; jj < 4; jj++)
                kk[jj] = *(const float4*)(Ks + (jj * 16 + tx) * FA_LD + d4 * 4);
#pragma unroll
            for (int i = 0; i < 4; i++)
#pragma unroll
                for (int jj = 0; jj < 4; jj++) {
                    s_[i][jj] = fmaf(a[i].x, kk[jj].x, s_[i][jj]);
                    s_[i][jj] = fmaf(a[i].y, kk[jj].y, s_[i][jj]);
                    s_[i][jj] = fmaf(a[i].z, kk[jj].z, s_[i][jj]);
                    s_[i][jj] = fmaf(a[i].w, kk[jj].w, s_[i][jj]);
                }
        }

        const float scale = 0.125f;
#pragma unroll
        for (int i = 0; i < 4; i++)
#pragma unroll
            for (int jj = 0; jj < 4; jj++) s_[i][jj] *= scale;

        if (j == qt) {
#pragma unroll
            for (int i = 0; i < 4; i++)
#pragma unroll
                for (int jj = 0; jj < 4; jj++)
                    if ((jj * 16 + tx) > (ty * 4 + i)) s_[i][jj] = -1e30f;
        }

#pragma unroll
        for (int i = 0; i < 4; i++) {
            float mx = fmaxf(fmaxf(s_[i][0], s_[i][1]), fmaxf(s_[i][2], s_[i][3]));
#pragma unroll
            for (int off = 1; off < 16; off <<= 1)
                mx = fmaxf(mx, __shfl_xor_sync(0xffffffffu, mx, off));
            float mnew = fmaxf(m_i[i], mx);
            float corr = __expf(m_i[i] - mnew);
            float rs = 0.0f;
#pragma unroll
            for (int jj = 0; jj < 4; jj++) {
                s_[i][jj] = __expf(s_[i][jj] - mnew);
                rs += s_[i][jj];
            }
#pragma unroll
            for (int off = 1; off < 16; off <<= 1)
                rs += __shfl_xor_sync(0xffffffffu, rs, off);
            l_i[i] = l_i[i] * corr + rs;
            m_i[i] = mnew;
#pragma unroll
            for (int jj = 0; jj < 4; jj++) o_[i][jj] *= corr;
        }

        __syncthreads();
#pragma unroll
        for (int i = 0; i < 4; i++)
#pragma unroll
            for (int jj = 0; jj < 4; jj++)
                Ks[(ty * 4 + i) * FA_LD + jj * 16 + tx] = s_[i][jj];
        __syncthreads();

#pragma unroll
        for (int c4 = 0; c4 < 16; c4++) {
            float4 p4[4];
#pragma unroll
            for (int i = 0; i < 4; i++)
                p4[i] = *(const float4*)(Ks + (ty * 4 + i) * FA_LD + c4 * 4);
#pragma unroll
            for (int cc = 0; cc < 4; cc++) {
                float vv[4];
#pragma unroll
                for (int jj = 0; jj < 4; jj++)
                    vv[jj] = Vs[(c4 * 4 + cc) * FA_LD + jj * 16 + tx];
#pragma unroll
                for (int i = 0; i < 4; i++) {
                    float pval = (cc == 0) ? p4[i].x : (cc == 1) ? p4[i].y
                               : (cc == 2) ? p4[i].z : p4[i].w;
#pragma unroll
                    for (int jj = 0; jj < 4; jj++)
                        o_[i][jj] = fmaf(pval, vv[jj], o_[i][jj]);
                }
            }
        }
    }

#pragma unroll
    for (int i = 0; i < 4; i++) {
        float rl = 1.0f / l_i[i];
        size_t row = (size_t)b * 1024 + (q0 + ty * 4 + i);
#pragma unroll
        for (int jj = 0; jj < 4; jj++)
            AO[row * 2048 + h * 64 + jj * 16 + tx] = o_[i][jj] * rl;
    }
}

// ---------------------------------------------------------------------------
// Launch
// ---------------------------------------------------------------------------
extern "C" void kernel_launch(void* const* d_in, const int* in_sizes, int n_in,
                              void* d_out, int out_size)
{
    const float* hs   = (const float*)d_in[0];
    const float* pk   = (const float*)d_in[1];
    const float* pv   = (const float*)d_in[2];
    const float* Wq   = (const float*)d_in[3];
    const float* Wk   = (const float*)d_in[4];
    const float* Wv   = (const float*)d_in[5];
    const float* Wo   = (const float*)d_in[6];
    const float* cosp = (const float*)d_in[7];
    const float* sinp = (const float*)d_in[8];
    float* out = (float*)d_out;

    float *Qb, *Kb, *Vb, *AO;
    cudaGetSymbolAddress((void**)&Qb, g_Q);
    cudaGetSymbolAddress((void**)&Kb, g_K);
    cudaGetSymbolAddress((void**)&Vb, g_V);
    cudaGetSymbolAddress((void**)&AO, g_AO);

    cudaFuncSetAttribute(flash_kernel,
                         cudaFuncAttributeMaxDynamicSharedMemorySize, FA_SMEM);

    // QKV projections on tensor pipe (tf32)
    gemm_tf32<<<dim3(16, 16), 256>>>(hs, Wq, Qb, 2048, 2048, 2048, 1, 0);
    gemm_tf32<<<dim3(2, 16),  256>>>(hs, Wk, Kb, 2048, 256,  2048, 1, NPREV);
    gemm_tf32<<<dim3(2, 16),  256>>>(hs, Wv, Vb, 2048, 256,  2048, 1, NPREV);

    // Cache gather + RoPE
    rope_gather_kernel<<<8192, 256>>>(pk, pv, cosp, sinp);

    // Causal flash attention -> g_AO [B, L, 2048]
    flash_kernel<<<dim3(16, 32, 2), 256, FA_SMEM>>>(Qb, Kb, Vb, AO);

    // Output projection (tf32)
    gemm_tf32<<<dim3(16, 16), 256>>>(AO, Wo, out, 2048, 2048, 2048, 0, 0);
}